// round 14
// baseline (speedup 1.0000x reference)
#include <cuda_runtime.h>
#include <cuda_fp16.h>
#include <cstdint>

#define BB 2
#define TT 4096
#define EE 512
#define HH 8
#define DD 64
#define MM (BB*TT)   // 8192

// Scratch (allocation-free rule: __device__ globals)
__device__ __half g_Xq[MM*EE];
__device__ __half g_Xk[MM*EE];
__device__ __half g_Xv[MM*EE];
__device__ __half g_Wq[EE*EE];
__device__ __half g_Wk[EE*EE];
__device__ __half g_Wv[EE*EE];
__device__ __half g_Wo[EE*EE];
__device__ __half g_Qh[MM*EE];
__device__ __half g_Kh[MM*EE];
__device__ __half g_Vh[MM*EE];
__device__ __half g_Ch[MM*EE];

// ===========================================================================
// helpers
// ===========================================================================
__device__ __forceinline__ uint32_t smem_u32(const void* p) {
    uint32_t a;
    asm("{ .reg .u64 t; cvta.to.shared.u64 t, %1; cvt.u32.u64 %0, t; }"
        : "=r"(a) : "l"(p));
    return a;
}

#define LDMX4(r0, r1, r2, r3, a) \
    asm volatile("ldmatrix.sync.aligned.m8n8.x4.shared.b16 {%0,%1,%2,%3}, [%4];" \
                 : "=r"(r0), "=r"(r1), "=r"(r2), "=r"(r3) : "r"(a))
#define LDMX4T(r0, r1, r2, r3, a) \
    asm volatile("ldmatrix.sync.aligned.m8n8.x4.trans.shared.b16 {%0,%1,%2,%3}, [%4];" \
                 : "=r"(r0), "=r"(r1), "=r"(r2), "=r"(r3) : "r"(a))

#define MMA16816(c, a, b0, b1) \
    asm volatile("mma.sync.aligned.m16n8k16.row.col.f32.f16.f16.f32 " \
                 "{%0,%1,%2,%3}, {%4,%5,%6,%7}, {%8,%9}, {%0,%1,%2,%3};" \
                 : "+f"((c)[0]), "+f"((c)[1]), "+f"((c)[2]), "+f"((c)[3]) \
                 : "r"((a)[0]), "r"((a)[1]), "r"((a)[2]), "r"((a)[3]), \
                   "r"(b0), "r"(b1))

#define CP16(dst, src) \
    asm volatile("cp.async.cg.shared.global [%0], [%1], 16;" :: "r"(dst), "l"(src))
#define CP_COMMIT() asm volatile("cp.async.commit_group;" ::: "memory")
#define CP_WAIT(N)  asm volatile("cp.async.wait_group %0;" :: "n"(N) : "memory")

__device__ __forceinline__ uint32_t packh2(float lo, float hi) {
    uint32_t u;
    asm("cvt.rn.f16x2.f32 %0, %1, %2;" : "=r"(u) : "f"(hi), "f"(lo));
    return u;
}
__device__ __forceinline__ uint32_t ex2h2(uint32_t y) {
    uint32_t r;
    asm("ex2.approx.f16x2 %0, %1;" : "=r"(r) : "r"(y));
    return r;
}
__device__ __forceinline__ uint32_t hadd2(uint32_t a, uint32_t b) {
    uint32_t r;
    asm("add.rn.f16x2 %0, %1, %2;" : "=r"(r) : "r"(a), "r"(b));
    return r;
}

#define SW(o) ((o) ^ (((o) >> 3) & 0x70))

// 0.125 * log2(e): folded into Q projection epilogue so S == ex2 exponent
#define QSCALE 0.1803368801111204f

// ===========================================================================
// fp32 -> fp16 conversion, fused multi-tensor variants
// ===========================================================================
__global__ __launch_bounds__(256) void cvt3(const float* __restrict__ a0,
                                            const float* __restrict__ a1,
                                            const float* __restrict__ a2,
                                            __half* __restrict__ o0,
                                            __half* __restrict__ o1,
                                            __half* __restrict__ o2) {
    const float* in  = (blockIdx.y == 0) ? a0 : (blockIdx.y == 1) ? a1 : a2;
    __half*      out = (blockIdx.y == 0) ? o0 : (blockIdx.y == 1) ? o1 : o2;
    int i = (blockIdx.x * 256 + threadIdx.x) * 8;
    float4 a = *(const float4*)(in + i);
    float4 b = *(const float4*)(in + i + 4);
    uint4 o;
    o.x = packh2(a.x, a.y); o.y = packh2(a.z, a.w);
    o.z = packh2(b.x, b.y); o.w = packh2(b.z, b.w);
    *(uint4*)(out + i) = o;
}

__global__ __launch_bounds__(256) void cvt4(const float* __restrict__ a0,
                                            const float* __restrict__ a1,
                                            const float* __restrict__ a2,
                                            const float* __restrict__ a3,
                                            __half* __restrict__ o0,
                                            __half* __restrict__ o1,
                                            __half* __restrict__ o2,
                                            __half* __restrict__ o3) {
    const float* in  = (blockIdx.y == 0) ? a0 : (blockIdx.y == 1) ? a1
                     : (blockIdx.y == 2) ? a2 : a3;
    __half*      out = (blockIdx.y == 0) ? o0 : (blockIdx.y == 1) ? o1
                     : (blockIdx.y == 2) ? o2 : o3;
    int i = (blockIdx.x * 256 + threadIdx.x) * 8;
    float4 a = *(const float4*)(in + i);
    float4 b = *(const float4*)(in + i + 4);
    uint4 o;
    o.x = packh2(a.x, a.y); o.y = packh2(a.z, a.w);
    o.z = packh2(b.x, b.y); o.w = packh2(b.z, b.w);
    *(uint4*)(out + i) = o;
}

// ===========================================================================
// fp16 tensor-core GEMM bodies — 3-stage ring (round-12, safe ordering)
// ===========================================================================
__device__ __forceinline__ void st2(__half* p, float a, float b) {
    *(uint32_t*)p = packh2(a, b);
}
__device__ __forceinline__ void st2(float* p, float a, float b) {
    *(float2*)p = make_float2(a, b);
}

#define GEMM_SMEM (98304 + 1024)

template <typename OutT>
__device__ __forceinline__ void gemm_body(const __half* __restrict__ X,
                                          const __half* __restrict__ W,
                                          const float* __restrict__ bias,
                                          OutT* __restrict__ OUT,
                                          int m0, int n0, float oscale,
                                          char* dyn) {
    const uint32_t sbase = (smem_u32(dyn) + 1023u) & ~1023u;

    const int tid  = threadIdx.x;
    const int w    = tid >> 5;
    const int lane = tid & 31;
    const int lr   = lane & 7;
    const int qlo  = (lane >> 3) & 1;
    const int qhi  = lane >> 4;

    const uint32_t cc = (uint32_t)(tid & 7);
    uint32_t soff[4];
    #pragma unroll
    for (int t = 0; t < 4; t++)
        soff[t] = SW(((uint32_t)(tid >> 3) + 32u * t) * 128u + cc * 16u);

    const __half* pX = X + (size_t)(m0 + (tid >> 3)) * EE + cc * 8;
    const __half* pW = W + (size_t)(n0 + (tid >> 3)) * EE + cc * 8;

    #pragma unroll
    for (int pre = 0; pre < 2; pre++) {
        const uint32_t bs = sbase + pre * 32768;
        #pragma unroll
        for (int t = 0; t < 4; t++) {
            CP16(bs + soff[t],         pX + t * 16384);
            CP16(bs + 16384 + soff[t], pW + t * 16384);
        }
        CP_COMMIT();
        pX += 64; pW += 64;
    }

    float sa[16][4];
    #pragma unroll
    for (int nt = 0; nt < 16; nt++)
        #pragma unroll
        for (int r = 0; r < 4; r++) sa[nt][r] = 0.0f;

    const int arow = 16 * w + lr + (qlo << 3);
    const int krow = lr + (qhi << 3);
    const int kchk = qlo << 4;

    int cur = 0, tgt = 2;
    for (int kc = 0; kc < 8; kc++) {
        __syncthreads();       // stage tgt free

        if (kc < 6) {
            const uint32_t nb = sbase + (uint32_t)tgt * 32768;
            #pragma unroll
            for (int t = 0; t < 4; t++) {
                CP16(nb + soff[t],         pX + t * 16384);
                CP16(nb + 16384 + soff[t], pW + t * 16384);
            }
            pX += 64; pW += 64;
        }
        CP_COMMIT();
        CP_WAIT(2);            // my chunk kc done
        __syncthreads();       // everyone's chunk kc done

        const uint32_t bs = sbase + (uint32_t)cur * 32768;

        uint32_t aa[4][4];
        #pragma unroll
        for (int ks = 0; ks < 4; ks++) {
            uint32_t a = bs + SW((uint32_t)(arow * 128 + ks * 32 + (qhi << 4)));
            LDMX4(aa[ks][0], aa[ks][1], aa[ks][2], aa[ks][3], a);
        }
        #pragma unroll
        for (int ks = 0; ks < 4; ks++) {
            #pragma unroll
            for (int p = 0; p < 8; p++) {
                uint32_t b0, b1, b2, b3;
                uint32_t a = bs + 16384 +
                             SW((uint32_t)((16 * p + krow) * 128 + ks * 32 + kchk));
                LDMX4(b0, b1, b2, b3, a);
                MMA16816(sa[2 * p],     aa[ks], b0, b1);
                MMA16816(sa[2 * p + 1], aa[ks], b2, b3);
            }
        }

        cur = (cur == 2) ? 0 : cur + 1;
        tgt = (tgt == 2) ? 0 : tgt + 1;
    }

    const int mr0 = m0 + 16 * w + (lane >> 2);
    #pragma unroll
    for (int nt = 0; nt < 16; nt++) {
        const int n = n0 + 8 * nt + 2 * (lane & 3);
        const float b0 = bias[n], b1 = bias[n + 1];
        st2(&OUT[(size_t)mr0 * EE + n],
            (sa[nt][0] + b0) * oscale, (sa[nt][1] + b1) * oscale);
        st2(&OUT[(size_t)(mr0 + 8) * EE + n],
            (sa[nt][2] + b0) * oscale, (sa[nt][3] + b1) * oscale);
    }
}

__global__ __launch_bounds__(256) void gemm_qkv(
    const __half* __restrict__ x0, const __half* __restrict__ x1,
    const __half* __restrict__ x2,
    const __half* __restrict__ w0, const __half* __restrict__ w1,
    const __half* __restrict__ w2,
    const float* __restrict__ b0, const float* __restrict__ b1,
    const float* __restrict__ b2,
    __half* __restrict__ o0, __half* __restrict__ o1,
    __half* __restrict__ o2) {
    extern __shared__ char dyn[];
    const int z = blockIdx.z;
    const __half* X = (z == 0) ? x0 : (z == 1) ? x1 : x2;
    const __half* W = (z == 0) ? w0 : (z == 1) ? w1 : w2;
    const float*  B = (z == 0) ? b0 : (z == 1) ? b1 : b2;
    __half*       O = (z == 0) ? o0 : (z == 1) ? o1 : o2;
    const float   s = (z == 0) ? QSCALE : 1.0f;
    gemm_body<__half>(X, W, B, O, blockIdx.y * 128, blockIdx.x * 128, s, dyn);
}

__global__ __launch_bounds__(256) void gemm_o(const __half* __restrict__ X,
                                              const __half* __restrict__ W,
                                              const float* __restrict__ bias,
                                              float* __restrict__ OUT) {
    extern __shared__ char dyn[];
    gemm_body<float>(X, W, bias, OUT, blockIdx.y * 128, blockIdx.x * 128, 1.0f, dyn);
}

// ===========================================================================
// FA2 attention — 4 warps x 32 q-rows (2 row-sets), 128-row blocks,
// KV tile processed in FOUR n-quarters (32 cols each) to keep the live
// register set ~200 (round-13's halves spilled at 255).
// SMEM: Q[16K] | buf0{K,V}[32K] | buf1{K,V}[32K] = 80K -> 2 blocks/SM.
// ===========================================================================
#define ATT_SMEM (81920 + 1024)

__global__ __launch_bounds__(128, 2) void attn_mma() {
    extern __shared__ char dyn[];
    const uint32_t dyn0 = smem_u32(dyn);
    const uint32_t sbase = (dyn0 + 1023u) & ~1023u;
    const uint32_t SQ = sbase;

    const int tid  = threadIdx.x;
    const int w    = tid >> 5;
    const int lane = tid & 31;
    const int lr   = lane & 7;
    const int qlo  = (lane >> 3) & 1;
    const int qhi  = lane >> 4;

    const int qt = blockIdx.x;                 // 128-row query tile, 0..31
    const int bh = blockIdx.y;
    const int b = bh / HH, h = bh % HH;

    const size_t gq = ((size_t)(b * TT + qt * 128)) * EE + (size_t)h * DD;
    const size_t gk = ((size_t)(b * TT)) * EE + (size_t)h * DD;

    // per-thread constant copy offsets
    const uint32_t rr = (uint32_t)(tid >> 3);
    const uint32_t cc = (uint32_t)(tid & 7);
    uint32_t soff[8];
    #pragma unroll
    for (int t = 0; t < 8; t++)
        soff[t] = SW((rr + 16u * t) * 128u + cc * 16u);
    const size_t gsrc = (size_t)rr * EE + cc * 8;

    // Q: 128 rows
    {
        const __half* pq = g_Qh + gq + gsrc;
        #pragma unroll
        for (int t = 0; t < 8; t++)
            CP16(SQ + soff[t], pq + t * 8192);
        CP_COMMIT();
    }

    // K/V prologue: tiles 0,1
    const __half* pk = g_Kh + gk + gsrc;
    const __half* pv = g_Vh + gk + gsrc;
    #pragma unroll
    for (int pre = 0; pre < 2; pre++) {
        const uint32_t kb = sbase + 16384 + pre * 32768;
        #pragma unroll
        for (int t = 0; t < 8; t++) {
            CP16(kb + soff[t],         pk + t * 8192);
            CP16(kb + 16384 + soff[t], pv + t * 8192);
        }
        CP_COMMIT();
        pk += 65536; pv += 65536;
    }

    CP_WAIT(2);
    __syncthreads();

    // Q fragments: 2 row-sets of 16 rows each
    uint32_t qa[2][4][4];
    #pragma unroll
    for (int s = 0; s < 2; s++) {
        int row = 32 * w + 16 * s + lr + (qlo << 3);
        #pragma unroll
        for (int ks = 0; ks < 4; ks++) {
            uint32_t a = SQ + SW((uint32_t)(row * 128 + ks * 32 + (qhi << 4)));
            LDMX4(qa[s][ks][0], qa[s][ks][1], qa[s][ks][2], qa[s][ks][3], a);
        }
    }

    const int krow = lr + (qhi << 3);
    const int kchk = qlo << 4;
    uint32_t sw_k[4];
    #pragma unroll
    for (int ks = 0; ks < 4; ks++)
        sw_k[ks] = SW((uint32_t)(krow * 128 + ks * 32 + kchk));

    const int vrow = lr + (qlo << 3);
    const int vchk = qhi << 4;
    uint32_t sw_v[4];
    #pragma unroll
    for (int q = 0; q < 4; q++)
        sw_v[q] = SW((uint32_t)(vrow * 128 + 32 * q + vchk));

    float oa[2][8][4] = {};
    float ls[2][2] = {};

    for (int kt = 0; kt < 32; kt++) {
        CP_WAIT(1);
        __syncthreads();
        const uint32_t kb = sbase + 16384 + (kt & 1) * 32768;
        const uint32_t vb = kb + 16384;

        uint32_t hs[2][2] = {};
        #pragma unroll
        for (int nq = 0; nq < 4; nq++) {
            const uint32_t nqoff = (uint32_t)(nq * 4096);   // 32 kv-rows

            // ---- S for this quarter, both row-sets ----
            float sa[2][4][4] = {};
            #pragma unroll
            for (int ks = 0; ks < 4; ks++) {
                const uint32_t kbase = kb + sw_k[ks] + nqoff;
                #pragma unroll
                for (int p = 0; p < 2; p++) {
                    uint32_t b0, b1, b2, b3;
                    LDMX4(b0, b1, b2, b3, kbase + (uint32_t)(p * 2048));
                    MMA16816(sa[0][2 * p],     qa[0][ks], b0, b1);
                    MMA16816(sa[0][2 * p + 1], qa[0][ks], b2, b3);
                    MMA16816(sa[1][2 * p],     qa[1][ks], b0, b1);
                    MMA16816(sa[1][2 * p + 1], qa[1][ks], b2, b3);
                }
            }

            // ---- exp ----
            uint32_t pf[2][4][2];
            #pragma unroll
            for (int s = 0; s < 2; s++)
                #pragma unroll
                for (int nt = 0; nt < 4; nt++) {
                    pf[s][nt][0] = ex2h2(packh2(sa[s][nt][0], sa[s][nt][1]));
                    pf[s][nt][1] = ex2h2(packh2(sa[s][nt][2], sa[s][nt][3]));
                    hs[s][0] = hadd2(hs[s][0], pf[s][nt][0]);
                    hs[s][1] = hadd2(hs[s][1], pf[s][nt][1]);
                }

            // ---- PV for this quarter (j in [32*nq, 32*nq+32)) ----
            #pragma unroll
            for (int kk = 0; kk < 2; kk++) {
                uint32_t pa0[4] = { pf[0][2 * kk][0], pf[0][2 * kk][1],
                                    pf[0][2 * kk + 1][0], pf[0][2 * kk + 1][1] };
                uint32_t pa1[4] = { pf[1][2 * kk][0], pf[1][2 * kk][1],
                                    pf[1][2 * kk + 1][0], pf[1][2 * kk + 1][1] };
                #pragma unroll
                for (int q = 0; q < 4; q++) {
                    uint32_t v0, v1, v2, v3;
                    LDMX4T(v0, v1, v2, v3,
                           vb + sw_v[q] + nqoff + (uint32_t)(kk * 2048));
                    MMA16816(oa[0][2 * q],     pa0, v0, v1);
                    MMA16816(oa[0][2 * q + 1], pa0, v2, v3);
                    MMA16816(oa[1][2 * q],     pa1, v0, v1);
                    MMA16816(oa[1][2 * q + 1], pa1, v2, v3);
                }
            }
        }

        // fold tile's f16x2 sums into fp32
        #pragma unroll
        for (int s = 0; s < 2; s++) {
            __half2 h0 = *reinterpret_cast<__half2*>(&hs[s][0]);
            __half2 h1 = *reinterpret_cast<__half2*>(&hs[s][1]);
            ls[s][0] += __low2float(h0) + __high2float(h0);
            ls[s][1] += __low2float(h1) + __high2float(h1);
        }

        __syncthreads();

        // prefetch tile kt+2 into the buffer just freed
        if (kt < 30) {
            #pragma unroll
            for (int t = 0; t < 8; t++) {
                CP16(kb + soff[t],         pk + t * 8192);
                CP16(kb + 16384 + soff[t], pv + t * 8192);
            }
            pk += 65536; pv += 65536;
        }
        CP_COMMIT();
    }

    #pragma unroll
    for (int s = 0; s < 2; s++)
        #pragma unroll
        for (int i = 0; i < 2; i++) {
            float l = ls[s][i];
            l += __shfl_xor_sync(0xFFFFFFFF, l, 1);
            l += __shfl_xor_sync(0xFFFFFFFF, l, 2);
            ls[s][i] = 1.0f / l;
        }

    #pragma unroll
    for (int s = 0; s < 2; s++) {
        const int m0 = qt * 128 + 32 * w + 16 * s + (lane >> 2);
        const size_t go = ((size_t)(b * TT + m0)) * EE + (size_t)h * DD
                          + 2 * (lane & 3);
        #pragma unroll
        for (int nt = 0; nt < 8; nt++) {
            *(uint32_t*)(g_Ch + go + 8 * nt) =
                packh2(oa[s][nt][0] * ls[s][0], oa[s][nt][1] * ls[s][0]);
            *(uint32_t*)(g_Ch + go + 8 * (size_t)EE + 8 * nt) =
                packh2(oa[s][nt][2] * ls[s][1], oa[s][nt][3] * ls[s][1]);
        }
    }
}

// ===========================================================================
// launch
// ===========================================================================
extern "C" void kernel_launch(void* const* d_in, const int* in_sizes, int n_in,
                              void* d_out, int out_size) {
    const float* query = (const float*)d_in[0];
    const float* key_  = (const float*)d_in[1];
    const float* value = (const float*)d_in[2];
    const float* Wq = (const float*)d_in[3];
    const float* bq = (const float*)d_in[4];
    const float* Wk = (const float*)d_in[5];
    const float* bk = (const float*)d_in[6];
    const float* Wv = (const float*)d_in[7];
    const float* bv = (const float*)d_in[8];
    const float* Wo = (const float*)d_in[9];
    const float* bo = (const float*)d_in[10];
    float* out = (float*)d_out;

    __half *xq, *xk, *xv, *wq, *wk, *wv, *wo, *qh, *kh, *vh, *ch;
    cudaGetSymbolAddress((void**)&xq, g_Xq);
    cudaGetSymbolAddress((void**)&xk, g_Xk);
    cudaGetSymbolAddress((void**)&xv, g_Xv);
    cudaGetSymbolAddress((void**)&wq, g_Wq);
    cudaGetSymbolAddress((void**)&wk, g_Wk);
    cudaGetSymbolAddress((void**)&wv, g_Wv);
    cudaGetSymbolAddress((void**)&wo, g_Wo);
    cudaGetSymbolAddress((void**)&qh, g_Qh);
    cudaGetSymbolAddress((void**)&kh, g_Kh);
    cudaGetSymbolAddress((void**)&vh, g_Vh);
    cudaGetSymbolAddress((void**)&ch, g_Ch);

    const int NX = MM * EE, NW = EE * EE;
    cvt3<<<dim3(NX / 8 / 256, 3), 256>>>(query, key_, value, xq, xk, xv);
    cvt4<<<dim3(NW / 8 / 256, 4), 256>>>(Wq, Wk, Wv, Wo, wq, wk, wv, wo);

    cudaFuncSetAttribute(gemm_qkv, cudaFuncAttributeMaxDynamicSharedMemorySize, GEMM_SMEM);
    cudaFuncSetAttribute(gemm_o,   cudaFuncAttributeMaxDynamicSharedMemorySize, GEMM_SMEM);

    gemm_qkv<<<dim3(EE / 128, MM / 128, 3), 256, GEMM_SMEM>>>(
        xq, xk, xv, wq, wk, wv, bq, bk, bv, qh, kh, vh);

    cudaFuncSetAttribute(attn_mma, cudaFuncAttributeMaxDynamicSharedMemorySize, ATT_SMEM);
    attn_mma<<<dim3(TT / 128, BB * HH), 128, ATT_SMEM>>>();

    gemm_o<<<dim3(EE / 128, MM / 128), 256, GEMM_SMEM>>>(ch, wo, bo, out);
}

// round 15
// speedup vs baseline: 1.1684x; 1.1684x over previous
#include <cuda_runtime.h>
#include <cuda_fp16.h>
#include <cstdint>

#define BB 2
#define TT 4096
#define EE 512
#define HH 8
#define DD 64
#define MM (BB*TT)   // 8192

// Scratch (allocation-free rule: __device__ globals)
__device__ __half g_Xq[MM*EE];
__device__ __half g_Xk[MM*EE];
__device__ __half g_Xv[MM*EE];
__device__ __half g_Wq[EE*EE];
__device__ __half g_Wk[EE*EE];
__device__ __half g_Wv[EE*EE];
__device__ __half g_Wo[EE*EE];
__device__ __half g_Qh[MM*EE];
__device__ __half g_Kh[MM*EE];
__device__ __half g_Vh[MM*EE];
__device__ __half g_Ch[MM*EE];

// ===========================================================================
// helpers
// ===========================================================================
__device__ __forceinline__ uint32_t smem_u32(const void* p) {
    uint32_t a;
    asm("{ .reg .u64 t; cvta.to.shared.u64 t, %1; cvt.u32.u64 %0, t; }"
        : "=r"(a) : "l"(p));
    return a;
}

#define LDMX4(r0, r1, r2, r3, a) \
    asm volatile("ldmatrix.sync.aligned.m8n8.x4.shared.b16 {%0,%1,%2,%3}, [%4];" \
                 : "=r"(r0), "=r"(r1), "=r"(r2), "=r"(r3) : "r"(a))
#define LDMX4T(r0, r1, r2, r3, a) \
    asm volatile("ldmatrix.sync.aligned.m8n8.x4.trans.shared.b16 {%0,%1,%2,%3}, [%4];" \
                 : "=r"(r0), "=r"(r1), "=r"(r2), "=r"(r3) : "r"(a))

#define MMA16816(c, a, b0, b1) \
    asm volatile("mma.sync.aligned.m16n8k16.row.col.f32.f16.f16.f32 " \
                 "{%0,%1,%2,%3}, {%4,%5,%6,%7}, {%8,%9}, {%0,%1,%2,%3};" \
                 : "+f"((c)[0]), "+f"((c)[1]), "+f"((c)[2]), "+f"((c)[3]) \
                 : "r"((a)[0]), "r"((a)[1]), "r"((a)[2]), "r"((a)[3]), \
                   "r"(b0), "r"(b1))

#define CP16(dst, src) \
    asm volatile("cp.async.cg.shared.global [%0], [%1], 16;" :: "r"(dst), "l"(src))
#define CP_COMMIT() asm volatile("cp.async.commit_group;" ::: "memory")
#define CP_WAIT(N)  asm volatile("cp.async.wait_group %0;" :: "n"(N) : "memory")

__device__ __forceinline__ uint32_t packh2(float lo, float hi) {
    uint32_t u;
    asm("cvt.rn.f16x2.f32 %0, %1, %2;" : "=r"(u) : "f"(hi), "f"(lo));
    return u;
}
__device__ __forceinline__ uint32_t ex2h2(uint32_t y) {
    uint32_t r;
    asm("ex2.approx.f16x2 %0, %1;" : "=r"(r) : "r"(y));
    return r;
}
__device__ __forceinline__ uint32_t hadd2(uint32_t a, uint32_t b) {
    uint32_t r;
    asm("add.rn.f16x2 %0, %1, %2;" : "=r"(r) : "r"(a), "r"(b));
    return r;
}

#define SW(o) ((o) ^ (((o) >> 3) & 0x70))

// 0.125 * log2(e): folded into Q projection epilogue so S == ex2 exponent
#define QSCALE 0.1803368801111204f

// ===========================================================================
// fp32 -> fp16 conversion: ALL 7 tensors in one launch.
// blocks [0, 6144): inputs (3 x 2048 blocks); [6144, 6656): weights (4 x 128).
// ===========================================================================
__global__ __launch_bounds__(256) void cvt_all(
    const float* __restrict__ a0, const float* __restrict__ a1,
    const float* __restrict__ a2,
    const float* __restrict__ w0, const float* __restrict__ w1,
    const float* __restrict__ w2, const float* __restrict__ w3,
    __half* __restrict__ o0, __half* __restrict__ o1, __half* __restrict__ o2,
    __half* __restrict__ p0, __half* __restrict__ p1, __half* __restrict__ p2,
    __half* __restrict__ p3) {
    const int bid = blockIdx.x;
    const float* in;
    __half* out;
    int blk;
    if (bid < 6144) {
        int which = bid >> 11;           // /2048
        blk = bid & 2047;
        in  = (which == 0) ? a0 : (which == 1) ? a1 : a2;
        out = (which == 0) ? o0 : (which == 1) ? o1 : o2;
    } else {
        int wb = bid - 6144;
        int which = wb >> 7;             // /128
        blk = wb & 127;
        in  = (which == 0) ? w0 : (which == 1) ? w1 : (which == 2) ? w2 : w3;
        out = (which == 0) ? p0 : (which == 1) ? p1 : (which == 2) ? p2 : p3;
    }
    int i = (blk * 256 + threadIdx.x) * 8;
    float4 a = *(const float4*)(in + i);
    float4 b = *(const float4*)(in + i + 4);
    uint4 o;
    o.x = packh2(a.x, a.y); o.y = packh2(a.z, a.w);
    o.z = packh2(b.x, b.y); o.w = packh2(b.z, b.w);
    *(uint4*)(out + i) = o;
}

// ===========================================================================
// fp16 tensor-core GEMM bodies — 3-stage ring, safe ordering:
//   sync (tgt free) -> prefetch kc+2 -> commit -> wait (my kc) -> sync -> compute
// SMEM: 3 stages x (A 16K + B 16K) = 96K (+1K align) -> 2 blocks/SM
// ===========================================================================
__device__ __forceinline__ void st2(__half* p, float a, float b) {
    *(uint32_t*)p = packh2(a, b);
}
__device__ __forceinline__ void st2(float* p, float a, float b) {
    *(float2*)p = make_float2(a, b);
}

#define GEMM_SMEM (98304 + 1024)

template <typename OutT>
__device__ __forceinline__ void gemm_body(const __half* __restrict__ X,
                                          const __half* __restrict__ W,
                                          const float* __restrict__ bias,
                                          OutT* __restrict__ OUT,
                                          int m0, int n0, float oscale,
                                          char* dyn) {
    const uint32_t sbase = (smem_u32(dyn) + 1023u) & ~1023u;

    const int tid  = threadIdx.x;
    const int w    = tid >> 5;
    const int lane = tid & 31;
    const int lr   = lane & 7;
    const int qlo  = (lane >> 3) & 1;
    const int qhi  = lane >> 4;

    const uint32_t cc = (uint32_t)(tid & 7);
    uint32_t soff[4];
    #pragma unroll
    for (int t = 0; t < 4; t++)
        soff[t] = SW(((uint32_t)(tid >> 3) + 32u * t) * 128u + cc * 16u);

    const __half* pX = X + (size_t)(m0 + (tid >> 3)) * EE + cc * 8;
    const __half* pW = W + (size_t)(n0 + (tid >> 3)) * EE + cc * 8;

    #pragma unroll
    for (int pre = 0; pre < 2; pre++) {
        const uint32_t bs = sbase + pre * 32768;
        #pragma unroll
        for (int t = 0; t < 4; t++) {
            CP16(bs + soff[t],         pX + t * 16384);
            CP16(bs + 16384 + soff[t], pW + t * 16384);
        }
        CP_COMMIT();
        pX += 64; pW += 64;
    }

    float sa[16][4];
    #pragma unroll
    for (int nt = 0; nt < 16; nt++)
        #pragma unroll
        for (int r = 0; r < 4; r++) sa[nt][r] = 0.0f;

    const int arow = 16 * w + lr + (qlo << 3);
    const int krow = lr + (qhi << 3);
    const int kchk = qlo << 4;

    int cur = 0, tgt = 2;
    for (int kc = 0; kc < 8; kc++) {
        __syncthreads();       // stage tgt free

        if (kc < 6) {
            const uint32_t nb = sbase + (uint32_t)tgt * 32768;
            #pragma unroll
            for (int t = 0; t < 4; t++) {
                CP16(nb + soff[t],         pX + t * 16384);
                CP16(nb + 16384 + soff[t], pW + t * 16384);
            }
            pX += 64; pW += 64;
        }
        CP_COMMIT();
        CP_WAIT(2);            // my chunk kc done
        __syncthreads();       // everyone's chunk kc done

        const uint32_t bs = sbase + (uint32_t)cur * 32768;

        uint32_t aa[4][4];
        #pragma unroll
        for (int ks = 0; ks < 4; ks++) {
            uint32_t a = bs + SW((uint32_t)(arow * 128 + ks * 32 + (qhi << 4)));
            LDMX4(aa[ks][0], aa[ks][1], aa[ks][2], aa[ks][3], a);
        }
        #pragma unroll
        for (int ks = 0; ks < 4; ks++) {
            #pragma unroll
            for (int p = 0; p < 8; p++) {
                uint32_t b0, b1, b2, b3;
                uint32_t a = bs + 16384 +
                             SW((uint32_t)((16 * p + krow) * 128 + ks * 32 + kchk));
                LDMX4(b0, b1, b2, b3, a);
                MMA16816(sa[2 * p],     aa[ks], b0, b1);
                MMA16816(sa[2 * p + 1], aa[ks], b2, b3);
            }
        }

        cur = (cur == 2) ? 0 : cur + 1;
        tgt = (tgt == 2) ? 0 : tgt + 1;
    }

    const int mr0 = m0 + 16 * w + (lane >> 2);
    #pragma unroll
    for (int nt = 0; nt < 16; nt++) {
        const int n = n0 + 8 * nt + 2 * (lane & 3);
        const float b0 = bias[n], b1 = bias[n + 1];
        st2(&OUT[(size_t)mr0 * EE + n],
            (sa[nt][0] + b0) * oscale, (sa[nt][1] + b1) * oscale);
        st2(&OUT[(size_t)(mr0 + 8) * EE + n],
            (sa[nt][2] + b0) * oscale, (sa[nt][3] + b1) * oscale);
    }
}

__global__ __launch_bounds__(256) void gemm_qkv(
    const __half* __restrict__ x0, const __half* __restrict__ x1,
    const __half* __restrict__ x2,
    const __half* __restrict__ w0, const __half* __restrict__ w1,
    const __half* __restrict__ w2,
    const float* __restrict__ b0, const float* __restrict__ b1,
    const float* __restrict__ b2,
    __half* __restrict__ o0, __half* __restrict__ o1,
    __half* __restrict__ o2) {
    extern __shared__ char dyn[];
    const int z = blockIdx.z;
    const __half* X = (z == 0) ? x0 : (z == 1) ? x1 : x2;
    const __half* W = (z == 0) ? w0 : (z == 1) ? w1 : w2;
    const float*  B = (z == 0) ? b0 : (z == 1) ? b1 : b2;
    __half*       O = (z == 0) ? o0 : (z == 1) ? o1 : o2;
    const float   s = (z == 0) ? QSCALE : 1.0f;
    gemm_body<__half>(X, W, B, O, blockIdx.y * 128, blockIdx.x * 128, s, dyn);
}

__global__ __launch_bounds__(256) void gemm_o(const __half* __restrict__ X,
                                              const __half* __restrict__ W,
                                              const float* __restrict__ bias,
                                              float* __restrict__ OUT) {
    extern __shared__ char dyn[];
    gemm_body<float>(X, W, bias, OUT, blockIdx.y * 128, blockIdx.x * 128, 1.0f, dyn);
}

// ===========================================================================
// FA2 attention — round-12 best config: 4 warps x 16 q-rows, 2-stage K/V,
// 3 blocks/SM, phased inner loop, f16x2 MUFU softmax, hoisted addressing.
// SMEM: Q[8K] | buf0{K,V}[32K] | buf1{K,V}[32K] = 72K (+1K align)
// ===========================================================================
#define ATT_SMEM (73728 + 1024)

__global__ __launch_bounds__(128, 3) void attn_mma() {
    extern __shared__ char dyn[];
    const uint32_t dyn0 = smem_u32(dyn);
    const uint32_t sbase = (dyn0 + 1023u) & ~1023u;
    const uint32_t SQ = sbase;

    const int tid  = threadIdx.x;
    const int w    = tid >> 5;
    const int lane = tid & 31;
    const int lr   = lane & 7;
    const int qlo  = (lane >> 3) & 1;
    const int qhi  = lane >> 4;

    const int qt = blockIdx.x;                 // 64-row query tile, 0..63
    const int bh = blockIdx.y;
    const int b = bh / HH, h = bh % HH;

    const size_t gq = ((size_t)(b * TT + qt * 64)) * EE + (size_t)h * DD;
    const size_t gk = ((size_t)(b * TT)) * EE + (size_t)h * DD;

    // per-thread constant copy offsets (hoisted out of the KV loop)
    const uint32_t rr = (uint32_t)(tid >> 3);
    const uint32_t cc = (uint32_t)(tid & 7);
    uint32_t soff[8];
    #pragma unroll
    for (int t = 0; t < 8; t++)
        soff[t] = SW((rr + 16u * t) * 128u + cc * 16u);
    const size_t gsrc = (size_t)rr * EE + cc * 8;

    // Q: 64 rows (t = 0..3)
    {
        const __half* pq = g_Qh + gq + gsrc;
        #pragma unroll
        for (int t = 0; t < 4; t++)
            CP16(SQ + soff[t], pq + t * 8192);
        CP_COMMIT();
    }

    // K/V rolling source pointers; prologue loads tiles 0,1
    const __half* pk = g_Kh + gk + gsrc;
    const __half* pv = g_Vh + gk + gsrc;
    #pragma unroll
    for (int pre = 0; pre < 2; pre++) {
        const uint32_t kb = sbase + 8192 + pre * 32768;
        #pragma unroll
        for (int t = 0; t < 8; t++) {
            CP16(kb + soff[t],         pk + t * 8192);
            CP16(kb + 16384 + soff[t], pv + t * 8192);
        }
        CP_COMMIT();
        pk += 65536; pv += 65536;                 // advance one 128-row tile
    }

    CP_WAIT(2);
    __syncthreads();
    uint32_t qa[4][4];
    {
        int row = 16 * w + lr + (qlo << 3);
        #pragma unroll
        for (int ks = 0; ks < 4; ks++) {
            uint32_t a = SQ + SW((uint32_t)(row * 128 + ks * 32 + (qhi << 4)));
            LDMX4(qa[ks][0], qa[ks][1], qa[ks][2], qa[ks][3], a);
        }
    }

    const int krow = lr + (qhi << 3);
    const int kchk = qlo << 4;
    uint32_t sw_k[4];
    #pragma unroll
    for (int ks = 0; ks < 4; ks++)
        sw_k[ks] = SW((uint32_t)(krow * 128 + ks * 32 + kchk));

    const int vrow = lr + (qlo << 3);
    const int vchk = qhi << 4;
    uint32_t sw_v[4];
    #pragma unroll
    for (int q = 0; q < 4; q++)
        sw_v[q] = SW((uint32_t)(vrow * 128 + 32 * q + vchk));

    float oa[8][4] = {};
    float lsum0 = 0.0f, lsum1 = 0.0f;

    for (int kt = 0; kt < 32; kt++) {
        CP_WAIT(1);
        __syncthreads();
        const uint32_t kb = sbase + 8192 + (kt & 1) * 32768;
        const uint32_t vb = kb + 16384;

        // ---- phase 1: S = Q K^T (16 independent accumulators) ----
        float sa[16][4];
        #pragma unroll
        for (int nt = 0; nt < 16; nt++)
            #pragma unroll
            for (int r = 0; r < 4; r++) sa[nt][r] = 0.0f;

        #pragma unroll
        for (int ks = 0; ks < 4; ks++) {
            const uint32_t kbase = kb + sw_k[ks];
            #pragma unroll
            for (int p = 0; p < 8; p++) {
                uint32_t b0, b1, b2, b3;
                LDMX4(b0, b1, b2, b3, kbase + (uint32_t)(p * 2048));
                MMA16816(sa[2 * p],     qa[ks], b0, b1);
                MMA16816(sa[2 * p + 1], qa[ks], b2, b3);
            }
        }

        // ---- phase 2: P = 2^S via f16x2 MUFU; rowsums in f16x2 ----
        uint32_t pf[16][2];
        uint32_t hs0 = 0, hs1 = 0;           // half2 zeros
        #pragma unroll
        for (int nt = 0; nt < 16; nt++) {
            pf[nt][0] = ex2h2(packh2(sa[nt][0], sa[nt][1]));
            pf[nt][1] = ex2h2(packh2(sa[nt][2], sa[nt][3]));
            hs0 = hadd2(hs0, pf[nt][0]);
            hs1 = hadd2(hs1, pf[nt][1]);
        }
        {
            __half2 h0 = *reinterpret_cast<__half2*>(&hs0);
            __half2 h1 = *reinterpret_cast<__half2*>(&hs1);
            lsum0 += __low2float(h0) + __high2float(h0);
            lsum1 += __low2float(h1) + __high2float(h1);
        }

        // ---- phase 3: O += P V ----
        #pragma unroll
        for (int kk = 0; kk < 8; kk++) {
            uint32_t pa[4] = { pf[2 * kk][0], pf[2 * kk][1],
                               pf[2 * kk + 1][0], pf[2 * kk + 1][1] };
            #pragma unroll
            for (int q = 0; q < 4; q++) {
                uint32_t v0, v1, v2, v3;
                LDMX4T(v0, v1, v2, v3, vb + sw_v[q] + (uint32_t)(kk * 2048));
                MMA16816(oa[2 * q],     pa, v0, v1);
                MMA16816(oa[2 * q + 1], pa, v2, v3);
            }
        }

        __syncthreads();

        // ---- prefetch tile kt+2 into the buffer just freed ----
        if (kt < 30) {
            #pragma unroll
            for (int t = 0; t < 8; t++) {
                CP16(kb + soff[t],         pk + t * 8192);
                CP16(kb + 16384 + soff[t], pv + t * 8192);
            }
            pk += 65536; pv += 65536;
        }
        CP_COMMIT();
    }

    lsum0 += __shfl_xor_sync(0xFFFFFFFF, lsum0, 1);
    lsum0 += __shfl_xor_sync(0xFFFFFFFF, lsum0, 2);
    lsum1 += __shfl_xor_sync(0xFFFFFFFF, lsum1, 1);
    lsum1 += __shfl_xor_sync(0xFFFFFFFF, lsum1, 2);
    const float il0 = 1.0f / lsum0;
    const float il1 = 1.0f / lsum1;

    const int m0 = qt * 64 + 16 * w + (lane >> 2);
    const size_t go = ((size_t)(b * TT + m0)) * EE + (size_t)h * DD + 2 * (lane & 3);
    #pragma unroll
    for (int nt = 0; nt < 8; nt++) {
        *(uint32_t*)(g_Ch + go + 8 * nt) =
            packh2(oa[nt][0] * il0, oa[nt][1] * il0);
        *(uint32_t*)(g_Ch + go + 8 * (size_t)EE + 8 * nt) =
            packh2(oa[nt][2] * il1, oa[nt][3] * il1);
    }
}

// ===========================================================================
// launch
// ===========================================================================
extern "C" void kernel_launch(void* const* d_in, const int* in_sizes, int n_in,
                              void* d_out, int out_size) {
    const float* query = (const float*)d_in[0];
    const float* key_  = (const float*)d_in[1];
    const float* value = (const float*)d_in[2];
    const float* Wq = (const float*)d_in[3];
    const float* bq = (const float*)d_in[4];
    const float* Wk = (const float*)d_in[5];
    const float* bk = (const float*)d_in[6];
    const float* Wv = (const float*)d_in[7];
    const float* bv = (const float*)d_in[8];
    const float* Wo = (const float*)d_in[9];
    const float* bo = (const float*)d_in[10];
    float* out = (float*)d_out;

    __half *xq, *xk, *xv, *wq, *wk, *wv, *wo, *qh, *kh, *vh, *ch;
    cudaGetSymbolAddress((void**)&xq, g_Xq);
    cudaGetSymbolAddress((void**)&xk, g_Xk);
    cudaGetSymbolAddress((void**)&xv, g_Xv);
    cudaGetSymbolAddress((void**)&wq, g_Wq);
    cudaGetSymbolAddress((void**)&wk, g_Wk);
    cudaGetSymbolAddress((void**)&wv, g_Wv);
    cudaGetSymbolAddress((void**)&wo, g_Wo);
    cudaGetSymbolAddress((void**)&qh, g_Qh);
    cudaGetSymbolAddress((void**)&kh, g_Kh);
    cudaGetSymbolAddress((void**)&vh, g_Vh);
    cudaGetSymbolAddress((void**)&ch, g_Ch);

    // 3 inputs: 2048 blocks each; 4 weights: 128 blocks each -> 6656 blocks
    cvt_all<<<6656, 256>>>(query, key_, value, Wq, Wk, Wv, Wo,
                           xq, xk, xv, wq, wk, wv, wo);

    cudaFuncSetAttribute(gemm_qkv, cudaFuncAttributeMaxDynamicSharedMemorySize, GEMM_SMEM);
    cudaFuncSetAttribute(gemm_o,   cudaFuncAttributeMaxDynamicSharedMemorySize, GEMM_SMEM);

    gemm_qkv<<<dim3(EE / 128, MM / 128, 3), 256, GEMM_SMEM>>>(
        xq, xk, xv, wq, wk, wv, bq, bk, bv, qh, kh, vh);

    cudaFuncSetAttribute(attn_mma, cudaFuncAttributeMaxDynamicSharedMemorySize, ATT_SMEM);
    attn_mma<<<dim3(TT / 64, BB * HH), 128, ATT_SMEM>>>();

    gemm_o<<<dim3(EE / 128, MM / 128), 256, GEMM_SMEM>>>(ch, wo, bo, out);
}

// round 16
// speedup vs baseline: 1.1881x; 1.0169x over previous
#include <cuda_runtime.h>
#include <cuda_fp16.h>
#include <cstdint>

#define BB 2
#define TT 4096
#define EE 512
#define HH 8
#define DD 64
#define MM (BB*TT)   // 8192

// Scratch (allocation-free rule: __device__ globals)
__device__ __half g_Xq[MM*EE];
__device__ __half g_Xk[MM*EE];
__device__ __half g_Xv[MM*EE];
__device__ __half g_Wq[EE*EE];
__device__ __half g_Wk[EE*EE];
__device__ __half g_Wv[EE*EE];
__device__ __half g_Wo[EE*EE];
__device__ __half g_Qh[MM*EE];
__device__ __half g_Kh[MM*EE];
__device__ __half g_Vh[MM*EE];
__device__ __half g_Ch[MM*EE];

// ===========================================================================
// helpers
// ===========================================================================
__device__ __forceinline__ uint32_t smem_u32(const void* p) {
    uint32_t a;
    asm("{ .reg .u64 t; cvta.to.shared.u64 t, %1; cvt.u32.u64 %0, t; }"
        : "=r"(a) : "l"(p));
    return a;
}

#define LDMX4(r0, r1, r2, r3, a) \
    asm volatile("ldmatrix.sync.aligned.m8n8.x4.shared.b16 {%0,%1,%2,%3}, [%4];" \
                 : "=r"(r0), "=r"(r1), "=r"(r2), "=r"(r3) : "r"(a))
#define LDMX4T(r0, r1, r2, r3, a) \
    asm volatile("ldmatrix.sync.aligned.m8n8.x4.trans.shared.b16 {%0,%1,%2,%3}, [%4];" \
                 : "=r"(r0), "=r"(r1), "=r"(r2), "=r"(r3) : "r"(a))

#define MMA16816(c, a, b0, b1) \
    asm volatile("mma.sync.aligned.m16n8k16.row.col.f32.f16.f16.f32 " \
                 "{%0,%1,%2,%3}, {%4,%5,%6,%7}, {%8,%9}, {%0,%1,%2,%3};" \
                 : "+f"((c)[0]), "+f"((c)[1]), "+f"((c)[2]), "+f"((c)[3]) \
                 : "r"((a)[0]), "r"((a)[1]), "r"((a)[2]), "r"((a)[3]), \
                   "r"(b0), "r"(b1))

// fp16-accumulate variant: D/C are 2x f16x2 regs ({row r pair}, {row r+8 pair})
#define MMA16816H(c01, a, b0, b1) \
    asm volatile("mma.sync.aligned.m16n8k16.row.col.f16.f16.f16.f16 " \
                 "{%0,%1}, {%2,%3,%4,%5}, {%6,%7}, {%0,%1};" \
                 : "+r"((c01)[0]), "+r"((c01)[1]) \
                 : "r"((a)[0]), "r"((a)[1]), "r"((a)[2]), "r"((a)[3]), \
                   "r"(b0), "r"(b1))

#define CP16(dst, src) \
    asm volatile("cp.async.cg.shared.global [%0], [%1], 16;" :: "r"(dst), "l"(src))
#define CP_COMMIT() asm volatile("cp.async.commit_group;" ::: "memory")
#define CP_WAIT(N)  asm volatile("cp.async.wait_group %0;" :: "n"(N) : "memory")

__device__ __forceinline__ uint32_t packh2(float lo, float hi) {
    uint32_t u;
    asm("cvt.rn.f16x2.f32 %0, %1, %2;" : "=r"(u) : "f"(hi), "f"(lo));
    return u;
}
__device__ __forceinline__ uint32_t ex2h2(uint32_t y) {
    uint32_t r;
    asm("ex2.approx.f16x2 %0, %1;" : "=r"(r) : "r"(y));
    return r;
}
__device__ __forceinline__ uint32_t hadd2(uint32_t a, uint32_t b) {
    uint32_t r;
    asm("add.rn.f16x2 %0, %1, %2;" : "=r"(r) : "r"(a), "r"(b));
    return r;
}

#define SW(o) ((o) ^ (((o) >> 3) & 0x70))

// 0.125 * log2(e): folded into Q projection epilogue so S == ex2 exponent
#define QSCALE 0.1803368801111204f

// ===========================================================================
// fp32 -> fp16 conversion: ALL 7 tensors in one launch.
// ===========================================================================
__global__ __launch_bounds__(256) void cvt_all(
    const float* __restrict__ a0, const float* __restrict__ a1,
    const float* __restrict__ a2,
    const float* __restrict__ w0, const float* __restrict__ w1,
    const float* __restrict__ w2, const float* __restrict__ w3,
    __half* __restrict__ o0, __half* __restrict__ o1, __half* __restrict__ o2,
    __half* __restrict__ p0, __half* __restrict__ p1, __half* __restrict__ p2,
    __half* __restrict__ p3) {
    const int bid = blockIdx.x;
    const float* in;
    __half* out;
    int blk;
    if (bid < 6144) {
        int which = bid >> 11;
        blk = bid & 2047;
        in  = (which == 0) ? a0 : (which == 1) ? a1 : a2;
        out = (which == 0) ? o0 : (which == 1) ? o1 : o2;
    } else {
        int wb = bid - 6144;
        int which = wb >> 7;
        blk = wb & 127;
        in  = (which == 0) ? w0 : (which == 1) ? w1 : (which == 2) ? w2 : w3;
        out = (which == 0) ? p0 : (which == 1) ? p1 : (which == 2) ? p2 : p3;
    }
    int i = (blk * 256 + threadIdx.x) * 8;
    float4 a = *(const float4*)(in + i);
    float4 b = *(const float4*)(in + i + 4);
    uint4 o;
    o.x = packh2(a.x, a.y); o.y = packh2(a.z, a.w);
    o.z = packh2(b.x, b.y); o.w = packh2(b.z, b.w);
    *(uint4*)(out + i) = o;
}

// ===========================================================================
// fp16 tensor-core GEMM bodies — 3-stage ring, safe ordering.
// ===========================================================================
__device__ __forceinline__ void st2(__half* p, float a, float b) {
    *(uint32_t*)p = packh2(a, b);
}
__device__ __forceinline__ void st2(float* p, float a, float b) {
    *(float2*)p = make_float2(a, b);
}

#define GEMM_SMEM (98304 + 1024)

template <typename OutT>
__device__ __forceinline__ void gemm_body(const __half* __restrict__ X,
                                          const __half* __restrict__ W,
                                          const float* __restrict__ bias,
                                          OutT* __restrict__ OUT,
                                          int m0, int n0, float oscale,
                                          char* dyn) {
    const uint32_t sbase = (smem_u32(dyn) + 1023u) & ~1023u;

    const int tid  = threadIdx.x;
    const int w    = tid >> 5;
    const int lane = tid & 31;
    const int lr   = lane & 7;
    const int qlo  = (lane >> 3) & 1;
    const int qhi  = lane >> 4;

    const uint32_t cc = (uint32_t)(tid & 7);
    uint32_t soff[4];
    #pragma unroll
    for (int t = 0; t < 4; t++)
        soff[t] = SW(((uint32_t)(tid >> 3) + 32u * t) * 128u + cc * 16u);

    const __half* pX = X + (size_t)(m0 + (tid >> 3)) * EE + cc * 8;
    const __half* pW = W + (size_t)(n0 + (tid >> 3)) * EE + cc * 8;

    #pragma unroll
    for (int pre = 0; pre < 2; pre++) {
        const uint32_t bs = sbase + pre * 32768;
        #pragma unroll
        for (int t = 0; t < 4; t++) {
            CP16(bs + soff[t],         pX + t * 16384);
            CP16(bs + 16384 + soff[t], pW + t * 16384);
        }
        CP_COMMIT();
        pX += 64; pW += 64;
    }

    float sa[16][4];
    #pragma unroll
    for (int nt = 0; nt < 16; nt++)
        #pragma unroll
        for (int r = 0; r < 4; r++) sa[nt][r] = 0.0f;

    const int arow = 16 * w + lr + (qlo << 3);
    const int krow = lr + (qhi << 3);
    const int kchk = qlo << 4;

    int cur = 0, tgt = 2;
    for (int kc = 0; kc < 8; kc++) {
        __syncthreads();       // stage tgt free

        if (kc < 6) {
            const uint32_t nb = sbase + (uint32_t)tgt * 32768;
            #pragma unroll
            for (int t = 0; t < 4; t++) {
                CP16(nb + soff[t],         pX + t * 16384);
                CP16(nb + 16384 + soff[t], pW + t * 16384);
            }
            pX += 64; pW += 64;
        }
        CP_COMMIT();
        CP_WAIT(2);            // my chunk kc done
        __syncthreads();       // everyone's chunk kc done

        const uint32_t bs = sbase + (uint32_t)cur * 32768;

        uint32_t aa[4][4];
        #pragma unroll
        for (int ks = 0; ks < 4; ks++) {
            uint32_t a = bs + SW((uint32_t)(arow * 128 + ks * 32 + (qhi << 4)));
            LDMX4(aa[ks][0], aa[ks][1], aa[ks][2], aa[ks][3], a);
        }
        #pragma unroll
        for (int ks = 0; ks < 4; ks++) {
            #pragma unroll
            for (int p = 0; p < 8; p++) {
                uint32_t b0, b1, b2, b3;
                uint32_t a = bs + 16384 +
                             SW((uint32_t)((16 * p + krow) * 128 + ks * 32 + kchk));
                LDMX4(b0, b1, b2, b3, a);
                MMA16816(sa[2 * p],     aa[ks], b0, b1);
                MMA16816(sa[2 * p + 1], aa[ks], b2, b3);
            }
        }

        cur = (cur == 2) ? 0 : cur + 1;
        tgt = (tgt == 2) ? 0 : tgt + 1;
    }

    const int mr0 = m0 + 16 * w + (lane >> 2);
    #pragma unroll
    for (int nt = 0; nt < 16; nt++) {
        const int n = n0 + 8 * nt + 2 * (lane & 3);
        const float b0 = bias[n], b1 = bias[n + 1];
        st2(&OUT[(size_t)mr0 * EE + n],
            (sa[nt][0] + b0) * oscale, (sa[nt][1] + b1) * oscale);
        st2(&OUT[(size_t)(mr0 + 8) * EE + n],
            (sa[nt][2] + b0) * oscale, (sa[nt][3] + b1) * oscale);
    }
}

__global__ __launch_bounds__(256) void gemm_qkv(
    const __half* __restrict__ x0, const __half* __restrict__ x1,
    const __half* __restrict__ x2,
    const __half* __restrict__ w0, const __half* __restrict__ w1,
    const __half* __restrict__ w2,
    const float* __restrict__ b0, const float* __restrict__ b1,
    const float* __restrict__ b2,
    __half* __restrict__ o0, __half* __restrict__ o1,
    __half* __restrict__ o2) {
    extern __shared__ char dyn[];
    const int z = blockIdx.z;
    const __half* X = (z == 0) ? x0 : (z == 1) ? x1 : x2;
    const __half* W = (z == 0) ? w0 : (z == 1) ? w1 : w2;
    const float*  B = (z == 0) ? b0 : (z == 1) ? b1 : b2;
    __half*       O = (z == 0) ? o0 : (z == 1) ? o1 : o2;
    const float   s = (z == 0) ? QSCALE : 1.0f;
    gemm_body<__half>(X, W, B, O, blockIdx.y * 128, blockIdx.x * 128, s, dyn);
}

__global__ __launch_bounds__(256) void gemm_o(const __half* __restrict__ X,
                                              const __half* __restrict__ W,
                                              const float* __restrict__ bias,
                                              float* __restrict__ OUT) {
    extern __shared__ char dyn[];
    gemm_body<float>(X, W, bias, OUT, blockIdx.y * 128, blockIdx.x * 128, 1.0f, dyn);
}

// ===========================================================================
// FA2 attention — round-12 structure; S-phase now uses FP16-ACCUM mma
// (probe for 2x legacy HMMA rate). sa: 64 -> 32 regs, and the f16x2 D
// layout IS the pf pack layout, so packh2 disappears from the exp phase.
// PV stays fp32-accum (4096-term sums).
// SMEM: Q[8K] | buf0{K,V}[32K] | buf1{K,V}[32K] = 72K (+1K align)
// ===========================================================================
#define ATT_SMEM (73728 + 1024)

__global__ __launch_bounds__(128, 3) void attn_mma() {
    extern __shared__ char dyn[];
    const uint32_t dyn0 = smem_u32(dyn);
    const uint32_t sbase = (dyn0 + 1023u) & ~1023u;
    const uint32_t SQ = sbase;

    const int tid  = threadIdx.x;
    const int w    = tid >> 5;
    const int lane = tid & 31;
    const int lr   = lane & 7;
    const int qlo  = (lane >> 3) & 1;
    const int qhi  = lane >> 4;

    const int qt = blockIdx.x;                 // 64-row query tile, 0..63
    const int bh = blockIdx.y;
    const int b = bh / HH, h = bh % HH;

    const size_t gq = ((size_t)(b * TT + qt * 64)) * EE + (size_t)h * DD;
    const size_t gk = ((size_t)(b * TT)) * EE + (size_t)h * DD;

    // per-thread constant copy offsets (hoisted out of the KV loop)
    const uint32_t rr = (uint32_t)(tid >> 3);
    const uint32_t cc = (uint32_t)(tid & 7);
    uint32_t soff[8];
    #pragma unroll
    for (int t = 0; t < 8; t++)
        soff[t] = SW((rr + 16u * t) * 128u + cc * 16u);
    const size_t gsrc = (size_t)rr * EE + cc * 8;

    // Q: 64 rows (t = 0..3)
    {
        const __half* pq = g_Qh + gq + gsrc;
        #pragma unroll
        for (int t = 0; t < 4; t++)
            CP16(SQ + soff[t], pq + t * 8192);
        CP_COMMIT();
    }

    // K/V rolling source pointers; prologue loads tiles 0,1
    const __half* pk = g_Kh + gk + gsrc;
    const __half* pv = g_Vh + gk + gsrc;
    #pragma unroll
    for (int pre = 0; pre < 2; pre++) {
        const uint32_t kb = sbase + 8192 + pre * 32768;
        #pragma unroll
        for (int t = 0; t < 8; t++) {
            CP16(kb + soff[t],         pk + t * 8192);
            CP16(kb + 16384 + soff[t], pv + t * 8192);
        }
        CP_COMMIT();
        pk += 65536; pv += 65536;                 // advance one 128-row tile
    }

    CP_WAIT(2);
    __syncthreads();
    uint32_t qa[4][4];
    {
        int row = 16 * w + lr + (qlo << 3);
        #pragma unroll
        for (int ks = 0; ks < 4; ks++) {
            uint32_t a = SQ + SW((uint32_t)(row * 128 + ks * 32 + (qhi << 4)));
            LDMX4(qa[ks][0], qa[ks][1], qa[ks][2], qa[ks][3], a);
        }
    }

    const int krow = lr + (qhi << 3);
    const int kchk = qlo << 4;
    uint32_t sw_k[4];
    #pragma unroll
    for (int ks = 0; ks < 4; ks++)
        sw_k[ks] = SW((uint32_t)(krow * 128 + ks * 32 + kchk));

    const int vrow = lr + (qlo << 3);
    const int vchk = qhi << 4;
    uint32_t sw_v[4];
    #pragma unroll
    for (int q = 0; q < 4; q++)
        sw_v[q] = SW((uint32_t)(vrow * 128 + 32 * q + vchk));

    float oa[8][4] = {};
    float lsum0 = 0.0f, lsum1 = 0.0f;

    for (int kt = 0; kt < 32; kt++) {
        CP_WAIT(1);
        __syncthreads();
        const uint32_t kb = sbase + 8192 + (kt & 1) * 32768;
        const uint32_t vb = kb + 16384;

        // ---- phase 1: S = Q K^T, FP16 accumulation (16 indep accum pairs) ----
        uint32_t sa[16][2];
        #pragma unroll
        for (int nt = 0; nt < 16; nt++) { sa[nt][0] = 0u; sa[nt][1] = 0u; }

        #pragma unroll
        for (int ks = 0; ks < 4; ks++) {
            const uint32_t kbase = kb + sw_k[ks];
            #pragma unroll
            for (int p = 0; p < 8; p++) {
                uint32_t b0, b1, b2, b3;
                LDMX4(b0, b1, b2, b3, kbase + (uint32_t)(p * 2048));
                MMA16816H(sa[2 * p],     qa[ks], b0, b1);
                MMA16816H(sa[2 * p + 1], qa[ks], b2, b3);
            }
        }

        // ---- phase 2: P = 2^S via f16x2 MUFU directly on packed S ----
        uint32_t pf[16][2];
        uint32_t hs0 = 0, hs1 = 0;
        #pragma unroll
        for (int nt = 0; nt < 16; nt++) {
            pf[nt][0] = ex2h2(sa[nt][0]);   // row r pair
            pf[nt][1] = ex2h2(sa[nt][1]);   // row r+8 pair
            hs0 = hadd2(hs0, pf[nt][0]);
            hs1 = hadd2(hs1, pf[nt][1]);
        }
        {
            __half2 h0 = *reinterpret_cast<__half2*>(&hs0);
            __half2 h1 = *reinterpret_cast<__half2*>(&hs1);
            lsum0 += __low2float(h0) + __high2float(h0);
            lsum1 += __low2float(h1) + __high2float(h1);
        }

        // ---- phase 3: O += P V (fp32 accum) ----
        #pragma unroll
        for (int kk = 0; kk < 8; kk++) {
            uint32_t pa[4] = { pf[2 * kk][0], pf[2 * kk][1],
                               pf[2 * kk + 1][0], pf[2 * kk + 1][1] };
            #pragma unroll
            for (int q = 0; q < 4; q++) {
                uint32_t v0, v1, v2, v3;
                LDMX4T(v0, v1, v2, v3, vb + sw_v[q] + (uint32_t)(kk * 2048));
                MMA16816(oa[2 * q],     pa, v0, v1);
                MMA16816(oa[2 * q + 1], pa, v2, v3);
            }
        }

        __syncthreads();

        // ---- prefetch tile kt+2 into the buffer just freed ----
        if (kt < 30) {
            #pragma unroll
            for (int t = 0; t < 8; t++) {
                CP16(kb + soff[t],         pk + t * 8192);
                CP16(kb + 16384 + soff[t], pv + t * 8192);
            }
            pk += 65536; pv += 65536;
        }
        CP_COMMIT();
    }

    lsum0 += __shfl_xor_sync(0xFFFFFFFF, lsum0, 1);
    lsum0 += __shfl_xor_sync(0xFFFFFFFF, lsum0, 2);
    lsum1 += __shfl_xor_sync(0xFFFFFFFF, lsum1, 1);
    lsum1 += __shfl_xor_sync(0xFFFFFFFF, lsum1, 2);
    const float il0 = 1.0f / lsum0;
    const float il1 = 1.0f / lsum1;

    const int m0 = qt * 64 + 16 * w + (lane >> 2);
    const size_t go = ((size_t)(b * TT + m0)) * EE + (size_t)h * DD + 2 * (lane & 3);
    #pragma unroll
    for (int nt = 0; nt < 8; nt++) {
        *(uint32_t*)(g_Ch + go + 8 * nt) =
            packh2(oa[nt][0] * il0, oa[nt][1] * il0);
        *(uint32_t*)(g_Ch + go + 8 * (size_t)EE + 8 * nt) =
            packh2(oa[nt][2] * il1, oa[nt][3] * il1);
    }
}

// ===========================================================================
// launch
// ===========================================================================
extern "C" void kernel_launch(void* const* d_in, const int* in_sizes, int n_in,
                              void* d_out, int out_size) {
    const float* query = (const float*)d_in[0];
    const float* key_  = (const float*)d_in[1];
    const float* value = (const float*)d_in[2];
    const float* Wq = (const float*)d_in[3];
    const float* bq = (const float*)d_in[4];
    const float* Wk = (const float*)d_in[5];
    const float* bk = (const float*)d_in[6];
    const float* Wv = (const float*)d_in[7];
    const float* bv = (const float*)d_in[8];
    const float* Wo = (const float*)d_in[9];
    const float* bo = (const float*)d_in[10];
    float* out = (float*)d_out;

    __half *xq, *xk, *xv, *wq, *wk, *wv, *wo, *qh, *kh, *vh, *ch;
    cudaGetSymbolAddress((void**)&xq, g_Xq);
    cudaGetSymbolAddress((void**)&xk, g_Xk);
    cudaGetSymbolAddress((void**)&xv, g_Xv);
    cudaGetSymbolAddress((void**)&wq, g_Wq);
    cudaGetSymbolAddress((void**)&wk, g_Wk);
    cudaGetSymbolAddress((void**)&wv, g_Wv);
    cudaGetSymbolAddress((void**)&wo, g_Wo);
    cudaGetSymbolAddress((void**)&qh, g_Qh);
    cudaGetSymbolAddress((void**)&kh, g_Kh);
    cudaGetSymbolAddress((void**)&vh, g_Vh);
    cudaGetSymbolAddress((void**)&ch, g_Ch);

    // 3 inputs: 2048 blocks each; 4 weights: 128 blocks each -> 6656 blocks
    cvt_all<<<6656, 256>>>(query, key_, value, Wq, Wk, Wv, Wo,
                           xq, xk, xv, wq, wk, wv, wo);

    cudaFuncSetAttribute(gemm_qkv, cudaFuncAttributeMaxDynamicSharedMemorySize, GEMM_SMEM);
    cudaFuncSetAttribute(gemm_o,   cudaFuncAttributeMaxDynamicSharedMemorySize, GEMM_SMEM);

    gemm_qkv<<<dim3(EE / 128, MM / 128, 3), 256, GEMM_SMEM>>>(
        xq, xk, xv, wq, wk, wv, bq, bk, bv, qh, kh, vh);

    cudaFuncSetAttribute(attn_mma, cudaFuncAttributeMaxDynamicSharedMemorySize, ATT_SMEM);
    attn_mma<<<dim3(TT / 64, BB * HH), 128, ATT_SMEM>>>();

    gemm_o<<<dim3(EE / 128, MM / 128), 256, GEMM_SMEM>>>(ch, wo, bo, out);
}